// round 5
// baseline (speedup 1.0000x reference)
#include <cuda_runtime.h>

// QHadamard: y = FWHT_4096(x) / 64, rows = 8192, DIM = 4096.
// 3 register passes of fwht16, 2 smem transposes, 0 shuffles, 16 elem/thread:
//   A: bits {8..11}  (thread T owns e{0..7}; k register = e{8..11})
//   B: bits {0..3}   (thread owns 16 contiguous elements; float4 smem, in-place)
//   C: bits {4..7}   (thread owns e{0..3} + e{8..11}; scalar smem read, dense-ish STG)
// Smem swizzle: phys(e) = e ^ (((e>>4)&7)<<2) ^ (((e>>8)&1)<<4)
// -- verified conflict-free for all four smem access phases.

#define DIM 4096
#define THREADS 256

__device__ __forceinline__ void bfly(float& a, float& b) {
    float t = a; a = t + b; b = t - b;
}

__device__ __forceinline__ void fwht16(float* x) {
#pragma unroll
    for (int h = 1; h < 16; h <<= 1)
#pragma unroll
        for (int i = 0; i < 16; i += (h << 1))
#pragma unroll
            for (int j = i; j < i + h; ++j) bfly(x[j], x[j + h]);
}

__global__ void __launch_bounds__(THREADS, 7)
QHadamard_24524263260380_kernel(const float* __restrict__ in,
                                float* __restrict__ out) {
    __shared__ float s[DIM];                       // 16 KB, swizzled layout

    const int    T   = threadIdx.x;                // 0..255
    const size_t row = (size_t)blockIdx.x * DIM;
    const float* g   = in + row;

    // ---- Pass A: e = T + k*256, k = 0..15 -> FWHT over bits {8..11} ----
    // Per warp instruction: 32 consecutive floats = one 128B line.
    float x[16];
#pragma unroll
    for (int k = 0; k < 16; ++k) x[k] = g[T + (k << 8)];

    const float scale = 0.015625f;                 // 1/sqrt(4096)
#pragma unroll
    for (int k = 0; k < 16; ++k) x[k] *= scale;

    fwht16(x);

    // ---- T1: scalar STS at phys(e) ----
    // e = T + (k<<8): (e>>4)&7 = (T>>4)&7, (e>>8)&1 = k&1.
    const int Tsw = T ^ (((T >> 4) & 7) << 2);
#pragma unroll
    for (int k = 0; k < 16; ++k) {
        s[(Tsw ^ ((k & 1) << 4)) + (k << 8)] = x[k];
    }
    __syncthreads();

    // ---- Pass B: thread owns e = T*16 + m -> FWHT over bits {0..3} ----
    // float4 logical index f = T*4 + j; phys_f4 = f ^ (T&7) ^ (((T>>4)&1)<<2).
    float4* s4 = reinterpret_cast<float4*>(s);
    const int bbase = (T * 4) ^ (T & 7) ^ (((T >> 4) & 1) << 2);
    float y[16];
#pragma unroll
    for (int j = 0; j < 4; ++j) {
        float4 v = s4[bbase ^ j];
        y[j*4+0] = v.x; y[j*4+1] = v.y; y[j*4+2] = v.z; y[j*4+3] = v.w;
    }
    fwht16(y);
#pragma unroll
    for (int j = 0; j < 4; ++j) {
        s4[bbase ^ j] = make_float4(y[j*4+0], y[j*4+1], y[j*4+2], y[j*4+3]);
    }
    __syncthreads();

    // ---- Pass C: thread owns lo = e{0..3}, hi = e{8..11}; r = e{4..7} ----
    const int lo = T & 15;
    const int hi = T >> 4;
    const int hx = (hi & 1) << 4;
    float z[16];
#pragma unroll
    for (int r = 0; r < 16; ++r) {
        z[r] = s[((lo + (r << 4) + (hi << 8)) ^ ((r & 7) << 2)) ^ hx];
    }

    fwht16(z);                                     // FWHT over bits {4..7}

    // ---- Store: e = lo + r*16 + hi*256 (two 64B segments per instr) ----
    float* o = out + row;
#pragma unroll
    for (int r = 0; r < 16; ++r) {
        o[lo + (r << 4) + (hi << 8)] = z[r];
    }
}

extern "C" void kernel_launch(void* const* d_in, const int* in_sizes, int n_in,
                              void* d_out, int out_size) {
    const float* x   = (const float*)d_in[0];
    float*       out = (float*)d_out;
    const int rows = in_sizes[0] / DIM;            // 8192
    QHadamard_24524263260380_kernel<<<rows, THREADS>>>(x, out);
}